// round 3
// baseline (speedup 1.0000x reference)
#include <cuda_runtime.h>
#include <math.h>

#define BSZ  1024
#define SLEN 512
#define TT   64
#define NW   4    // warps (=chains) per block
#define KRN  6    // renormalize every KRN unmasked steps (exact pow-2 scaling)

__device__ unsigned long long g_acc;
__device__ int                g_cnt;

static __device__ __forceinline__ unsigned long long pk2(float x, float y) {
    unsigned long long r;
    asm("mov.b64 %0, {%1, %2};" : "=l"(r) : "f"(x), "f"(y));
    return r;
}
static __device__ __forceinline__ float2 upk2(unsigned long long v) {
    float2 r;
    asm("mov.b64 {%0, %1}, %2;" : "=f"(r.x), "=f"(r.y) : "l"(v));
    return r;
}
// Packed fp32x2 FMA (Blackwell): both halves independent MACs -> SASS FFMA2
static __device__ __forceinline__ unsigned long long ffma2(unsigned long long a,
                                                           unsigned long long b,
                                                           unsigned long long c) {
    unsigned long long d;
    asm("fma.rn.f32x2 %0, %1, %2, %3;" : "=l"(d) : "l"(a), "l"(b), "l"(c));
    return d;
}
static __device__ __forceinline__ unsigned long long fadd2(unsigned long long a,
                                                           unsigned long long b) {
    unsigned long long d;
    asm("add.rn.f32x2 %0, %1, %2;" : "=l"(d) : "l"(a), "l"(b));
    return d;
}

__global__ __launch_bounds__(NW * 32, 2)
void crf_forward(const float* __restrict__ e, const int* __restrict__ tags,
                 const unsigned char* __restrict__ mask,
                 const float* __restrict__ st, const float* __restrict__ et,
                 const float* __restrict__ tmat)
{
    // p vector per warp, double buffered: 32 float2 per buffer (64 floats, NOT duplicated)
    __shared__ __align__(16) float2 pbuf[NW][2][32];

    const int w     = threadIdx.x >> 5;
    const int lane  = threadIdx.x & 31;
    const int chain = blockIdx.x * NW + w;
    const int c0 = 2 * lane, c1 = c0 + 1;   // this lane's two columns (adjacent!)

    const float*         eb = e    + (size_t)chain * (SLEN * TT);
    const int*           tb = tags + chain * SLEN;
    const unsigned char* mb = mask + chain * SLEN;

    // ---- exp(transition) in registers, paired over adjacent i for fixed column ----
    // EpA[m] = (E[2m][c0], E[2m+1][c0]),  EpB[m] = (E[2m][c1], E[2m+1][c1])
    unsigned long long EpA[32], EpB[32];
#pragma unroll
    for (int m = 0; m < 32; ++m) {
        float a0 = expf(__ldg(&tmat[(2 * m)     * TT + c0]));
        float a1 = expf(__ldg(&tmat[(2 * m + 1) * TT + c0]));
        float b0 = expf(__ldg(&tmat[(2 * m)     * TT + c1]));
        float b1 = expf(__ldg(&tmat[(2 * m + 1) * TT + c1]));
        EpA[m] = pk2(a0, a1);
        EpB[m] = pk2(b0, b1);
    }

    // ---- tag-path score + mask count ----
    float scp = 0.f;
    int cntp = 0;
#pragma unroll 1
    for (int s = lane; s < SLEN; s += 32) {
        int m = mb[s];
        cntp += m;
        if (s > 0 && m) {
            int tp = tb[s - 1], tn = tb[s];
            scp += __ldg(&tmat[tp * TT + tn]) + eb[s * TT + tn];
        }
    }
#pragma unroll
    for (int off = 16; off; off >>= 1) {
        scp  += __shfl_xor_sync(0xffffffffu, scp, off);
        cntp += __shfl_xor_sync(0xffffffffu, cntp, off);
    }
    int   t0    = tb[0];
    int   tlast = tb[cntp - 1];
    float score = scp + st[t0] + eb[t0] + et[tlast];

    // ---- forward-vector init (step 0) ----
    float2 ev0 = *reinterpret_cast<const float2*>(eb + c0);
    float n0 = st[c0] + ev0.x;
    float n1 = st[c1] + ev0.y;
    float base = fmaxf(n0, n1);
#pragma unroll
    for (int off = 16; off; off >>= 1)
        base = fmaxf(base, __shfl_xor_sync(0xffffffffu, base, off));
    float p0 = __expf(n0 - base);
    float p1 = __expf(n1 - base);
    pbuf[w][0][lane] = make_float2(p0, p1);
    int cur  = 0;
    int Eacc = 0;   // accumulated power-of-two scale (exact)
    int rc   = 0;   // steps since last renorm
    __syncwarp();

    // one recursion step: q_c = (sum_i p_i E[i][c]) * exp(e_c); renorm every KRN steps
    auto do_step = [&](float2 ec, int mk) {
        if (!mk) return;
        float F0 = __expf(ec.x);
        float F1 = __expf(ec.y);
        const float4* rp = reinterpret_cast<const float4*>(pbuf[w][cur]);
        unsigned long long accA[4] = {0ull, 0ull, 0ull, 0ull};
        unsigned long long accB[4] = {0ull, 0ull, 0ull, 0ull};
#pragma unroll
        for (int l = 0; l < 16; ++l) {
            float4 v = rp[l];                       // p[4l..4l+3]
            unsigned long long x = pk2(v.x, v.y);   // pair index 2l
            unsigned long long y = pk2(v.z, v.w);   // pair index 2l+1
            accA[(2 * l)     & 3] = ffma2(x, EpA[2 * l],     accA[(2 * l)     & 3]);
            accA[(2 * l + 1) & 3] = ffma2(y, EpA[2 * l + 1], accA[(2 * l + 1) & 3]);
            accB[(2 * l)     & 3] = ffma2(x, EpB[2 * l],     accB[(2 * l)     & 3]);
            accB[(2 * l + 1) & 3] = ffma2(y, EpB[2 * l + 1], accB[(2 * l + 1) & 3]);
        }
        float2 qa = upk2(fadd2(fadd2(accA[0], accA[1]), fadd2(accA[2], accA[3])));
        float2 qb = upk2(fadd2(fadd2(accB[0], accB[1]), fadd2(accB[2], accB[3])));
        float q0 = (qa.x + qa.y) * F0;
        float q1 = (qb.x + qb.y) * F1;
        if (++rc >= KRN) {          // amortized exact pow-2 renormalization
            rc = 0;
            float loc = fmaxf(q0, q1);
#pragma unroll
            for (int off = 16; off; off >>= 1)
                loc = fmaxf(loc, __shfl_xor_sync(0xffffffffu, loc, off));
            int ke = (__float_as_int(loc) >> 23) - 127;     // floor(log2(max q))
            Eacc += ke;
            float rinv = __int_as_float((127 - ke) << 23);  // exact 2^-ke
            q0 *= rinv;
            q1 *= rinv;
        }
        p0 = q0;
        p1 = q1;
        cur ^= 1;
        pbuf[w][cur][lane] = make_float2(p0, p1);
        __syncwarp();
    };

    // ---- main loop, software prefetch distance 2, unrolled x2 ----
    float2 pfA = *reinterpret_cast<const float2*>(eb + 1 * TT + c0); int mA = mb[1];
    float2 pfB = *reinterpret_cast<const float2*>(eb + 2 * TT + c0); int mB = mb[2];
#pragma unroll 1
    for (int s = 1; s < SLEN; s += 2) {
        float2 ec = pfA; int mk = mA;
        if (s + 2 < SLEN) {
            pfA = *reinterpret_cast<const float2*>(eb + (s + 2) * TT + c0);
            mA  = mb[s + 2];
        }
        do_step(ec, mk);
        float2 ec2 = pfB; int mk2 = mB;
        if (s + 3 < SLEN) {
            pfB = *reinterpret_cast<const float2*>(eb + (s + 3) * TT + c0);
            mB  = mb[s + 3];
        }
        if (s + 1 < SLEN) do_step(ec2, mk2);
    }

    // ---- logZ and deterministic fixed-point accumulation ----
    float z = p0 * __expf(et[c0]) + p1 * __expf(et[c1]);
#pragma unroll
    for (int off = 16; off; off >>= 1)
        z += __shfl_xor_sync(0xffffffffu, z, off);
    if (lane == 0) {
        double logZ = (double)base + (double)Eacc * 0.6931471805599453094
                    + log((double)z);
        double val  = (double)score - logZ;
        long long fx = llrint(val * 1048576.0);               // 2^20 fixed point
        atomicAdd(&g_acc, (unsigned long long)fx);            // deterministic (integer)
        atomicAdd(&g_cnt, cntp);
    }
}

__global__ void crf_zero()
{
    g_acc = 0ull;
    g_cnt = 0;
}

__global__ void crf_final(float* __restrict__ out)
{
    out[0] = (float)((double)(long long)g_acc * (1.0 / 1048576.0) / (double)g_cnt);
}

extern "C" void kernel_launch(void* const* d_in, const int* in_sizes, int n_in,
                              void* d_out, int out_size)
{
    const float*         e    = (const float*)d_in[0];
    const int*           tags = (const int*)d_in[1];
    const unsigned char* mask = (const unsigned char*)d_in[2];
    const float*         st   = (const float*)d_in[3];
    const float*         et   = (const float*)d_in[4];
    const float*         t    = (const float*)d_in[5];

    crf_zero<<<1, 1>>>();
    crf_forward<<<BSZ / NW, NW * 32>>>(e, tags, mask, st, et, t);
    crf_final<<<1, 1>>>((float*)d_out);
}

// round 4
// speedup vs baseline: 1.5525x; 1.5525x over previous
#include <cuda_runtime.h>
#include <math.h>

#define BSZ  1024
#define SLEN 512
#define TT   64
#define NW   4    // warps (=chains) per block
#define KRN  6    // renormalize every KRN unmasked steps (exact pow-2 scaling)

__device__ double g_res[BSZ];
__device__ int    g_cnt[BSZ];
__device__ int    g_ticket;    // zero-init; last block resets to 0 (replay-safe)

static __device__ __forceinline__ unsigned long long pk2(float x, float y) {
    unsigned long long r;
    asm("mov.b64 %0, {%1, %2};" : "=l"(r) : "f"(x), "f"(y));
    return r;
}
static __device__ __forceinline__ float2 upk2(unsigned long long v) {
    float2 r;
    asm("mov.b64 {%0, %1}, %2;" : "=f"(r.x), "=f"(r.y) : "l"(v));
    return r;
}
// Packed fp32x2 FMA (Blackwell): both halves independent MACs -> SASS FFMA2
static __device__ __forceinline__ unsigned long long ffma2(unsigned long long a,
                                                           unsigned long long b,
                                                           unsigned long long c) {
    unsigned long long d;
    asm("fma.rn.f32x2 %0, %1, %2, %3;" : "=l"(d) : "l"(a), "l"(b), "l"(c));
    return d;
}
static __device__ __forceinline__ unsigned long long fadd2(unsigned long long a,
                                                           unsigned long long b) {
    unsigned long long d;
    asm("add.rn.f32x2 %0, %1, %2;" : "=l"(d) : "l"(a), "l"(b));
    return d;
}

__global__ __launch_bounds__(NW * 32, 2)
void crf_forward(const float* __restrict__ e, const int* __restrict__ tags,
                 const unsigned char* __restrict__ mask,
                 const float* __restrict__ st, const float* __restrict__ et,
                 const float* __restrict__ tmat, float* __restrict__ out)
{
    // duplicated-p arrays, double buffered per warp: pd[w][buf][i] = (p_i, p_i)
    __shared__ __align__(16) unsigned long long pd[NW][2][TT];
    __shared__ int s_ticket;

    const int w     = threadIdx.x >> 5;
    const int lane  = threadIdx.x & 31;
    const int chain = blockIdx.x * NW + w;
    const int j0 = lane, j1 = lane + 32;

    const float*         eb = e    + (size_t)chain * (SLEN * TT);
    const int*           tb = tags + chain * SLEN;
    const unsigned char* mb = mask + chain * SLEN;

    // ---- exp(transition) in registers: lane holds columns j0 and j1 packed ----
    unsigned long long Ep[TT];
#pragma unroll
    for (int i = 0; i < TT; ++i) {
        float a = __expf(__ldg(&tmat[i * TT + j0]));
        float b = __expf(__ldg(&tmat[i * TT + j1]));
        Ep[i] = pk2(a, b);
    }

    // ---- tag-path score + mask count (gathers, lanes stride over s) ----
    float scp = 0.f;
    int cntp = 0;
#pragma unroll 1
    for (int s = lane; s < SLEN; s += 32) {
        int m = mb[s];
        cntp += m;
        if (s > 0 && m) {
            int tp = tb[s - 1], tn = tb[s];
            scp += __ldg(&tmat[tp * TT + tn]) + eb[s * TT + tn];
        }
    }
#pragma unroll
    for (int off = 16; off; off >>= 1) {
        scp  += __shfl_xor_sync(0xffffffffu, scp, off);
        cntp += __shfl_xor_sync(0xffffffffu, cntp, off);
    }
    int   t0    = tb[0];
    int   tlast = tb[cntp - 1];
    float score = scp + st[t0] + eb[t0] + et[tlast];

    // ---- forward-vector init (step 0) ----
    float n0 = st[j0] + eb[j0];
    float n1 = st[j1] + eb[j1];
    float base = fmaxf(n0, n1);
#pragma unroll
    for (int off = 16; off; off >>= 1)
        base = fmaxf(base, __shfl_xor_sync(0xffffffffu, base, off));
    float p0 = __expf(n0 - base);
    float p1 = __expf(n1 - base);
    pd[w][0][j0] = pk2(p0, p0);
    pd[w][0][j1] = pk2(p1, p1);
    int cur  = 0;
    int Eacc = 0;   // accumulated power-of-two scale (exact)
    int rc   = 0;   // unmasked steps since last renorm
    __syncwarp();

    // one recursion step: q = (p . E) * exp(e_s); exact pow-2 renorm every KRN steps
    auto do_step = [&](float e0, float e1, int mk) {
        if (!mk) return;
        float F0 = __expf(e0);
        float F1 = __expf(e1);
        const ulonglong2* rp = reinterpret_cast<const ulonglong2*>(pd[w][cur]);
        unsigned long long a0 = 0ull, a1 = 0ull, a2 = 0ull, a3 = 0ull;
#pragma unroll
        for (int k = 0; k < 32; k += 2) {
            ulonglong2 v0 = rp[k];
            ulonglong2 v1 = rp[k + 1];
            a0 = ffma2(v0.x, Ep[2 * k],     a0);
            a1 = ffma2(v0.y, Ep[2 * k + 1], a1);
            a2 = ffma2(v1.x, Ep[2 * k + 2], a2);
            a3 = ffma2(v1.y, Ep[2 * k + 3], a3);
        }
        float2 q = upk2(fadd2(fadd2(a0, a1), fadd2(a2, a3)));
        float q0 = q.x * F0;
        float q1 = q.y * F1;
        if (++rc >= KRN) {      // amortized exact pow-2 renormalization
            rc = 0;
            float loc = fmaxf(q0, q1);
#pragma unroll
            for (int off = 16; off; off >>= 1)
                loc = fmaxf(loc, __shfl_xor_sync(0xffffffffu, loc, off));
            int ke = (__float_as_int(loc) >> 23) - 127;     // floor(log2(max q))
            Eacc += ke;
            float rinv = __int_as_float((127 - ke) << 23);  // exact 2^-ke
            q0 *= rinv;
            q1 *= rinv;
        }
        p0 = q0;
        p1 = q1;
        cur ^= 1;
        pd[w][cur][j0] = pk2(p0, p0);
        pd[w][cur][j1] = pk2(p1, p1);
        __syncwarp();
    };

    // ---- main loop, software prefetch distance 2, unrolled x2 ----
    float A0 = eb[1 * TT + j0], A1 = eb[1 * TT + j1]; int Am = mb[1];
    float B0 = eb[2 * TT + j0], B1 = eb[2 * TT + j1]; int Bm = mb[2];
#pragma unroll 1
    for (int s = 1; s < SLEN; s += 2) {
        float e0 = A0, e1 = A1; int mk = Am;
        int sp = s + 2;
        if (sp < SLEN) { A0 = eb[sp * TT + j0]; A1 = eb[sp * TT + j1]; Am = mb[sp]; }
        do_step(e0, e1, mk);
        if (s + 1 < SLEN) {
            float f0 = B0, f1 = B1; int mk2 = Bm;
            int sq = s + 3;
            if (sq < SLEN) { B0 = eb[sq * TT + j0]; B1 = eb[sq * TT + j1]; Bm = mb[sq]; }
            do_step(f0, f1, mk2);
        }
    }

    // ---- logZ, per-chain result ----
    float z = p0 * __expf(et[j0]) + p1 * __expf(et[j1]);
#pragma unroll
    for (int off = 16; off; off >>= 1)
        z += __shfl_xor_sync(0xffffffffu, z, off);
    if (lane == 0) {
        double logZ = (double)base + (double)Eacc * 0.6931471805599453094
                    + log((double)z);
        g_res[chain] = (double)score - logZ;
        g_cnt[chain] = cntp;
    }

    // ---- last-block fused finalization (deterministic: one block, fixed order) ----
    __syncthreads();
    if (threadIdx.x == 0) {
        __threadfence();
        s_ticket = atomicAdd(&g_ticket, 1);
    }
    __syncthreads();
    if (s_ticket == gridDim.x - 1) {
        int tid = threadIdx.x;              // 128 threads
        double acc = 0.0;
        int    cnt = 0;
#pragma unroll
        for (int i = 0; i < BSZ / (NW * 32); ++i) {   // 8 chains per thread
            int idx = tid + i * (NW * 32);
            acc += g_res[idx];
            cnt += g_cnt[idx];
        }
#pragma unroll
        for (int off = 16; off; off >>= 1) {
            acc += __shfl_xor_sync(0xffffffffu, acc, off);
            cnt += __shfl_xor_sync(0xffffffffu, cnt, off);
        }
        __shared__ double sacc[NW];
        __shared__ int    scnt[NW];
        if (lane == 0) { sacc[w] = acc; scnt[w] = cnt; }
        __syncthreads();
        if (threadIdx.x == 0) {
            double ta = 0.0; int tc = 0;
#pragma unroll
            for (int i = 0; i < NW; ++i) { ta += sacc[i]; tc += scnt[i]; }
            out[0] = (float)(ta / (double)tc);
            g_ticket = 0;                    // reset for next graph replay
        }
    }
}

extern "C" void kernel_launch(void* const* d_in, const int* in_sizes, int n_in,
                              void* d_out, int out_size)
{
    const float*         e    = (const float*)d_in[0];
    const int*           tags = (const int*)d_in[1];
    const unsigned char* mask = (const unsigned char*)d_in[2];
    const float*         st   = (const float*)d_in[3];
    const float*         et   = (const float*)d_in[4];
    const float*         t    = (const float*)d_in[5];

    crf_forward<<<BSZ / NW, NW * 32>>>(e, tags, mask, st, et, t, (float*)d_out);
}